// round 1
// baseline (speedup 1.0000x reference)
#include <cuda_runtime.h>
#include <math.h>

#define BATCH 16384
#define DIM 64
#define LAMBDA 0.01f

__global__ void zero_out_kernel(float* out) {
    out[0] = 0.0f;
}

// 16 threads per row (16 x float4 = 64 floats). 256 threads/block = 16 rows/block.
// grid = BATCH/16 = 1024 blocks.
__global__ void __launch_bounds__(256) pmf_kernel(
    const int* __restrict__ u,
    const int* __restrict__ iidx,
    const int* __restrict__ s,
    const float4* __restrict__ W4,   // [USER_SIZE * 16]
    const float4* __restrict__ H4,   // [ITEM_SIZE * 16]
    float* __restrict__ out)
{
    const int tid  = threadIdx.x;
    const int grp  = tid >> 4;          // 0..15 group within block
    const int lane = tid & 15;          // 0..15 lane within group
    const int row  = blockIdx.x * 16 + grp;

    float dot = 0.0f;
    float reg = 0.0f;

    if (row < BATCH) {
        const int ur = u[row];
        const int ir = iidx[row];
        float4 a = __ldg(&W4[(size_t)ur * 16 + lane]);
        float4 b = __ldg(&H4[(size_t)ir * 16 + lane]);
        dot = a.x * b.x + a.y * b.y + a.z * b.z + a.w * b.w;
        reg = LAMBDA * (a.x * a.x + a.y * a.y + a.z * a.z + a.w * a.w
                      + b.x * b.x + b.y * b.y + b.z * b.z + b.w * b.w);
    }

    // reduce dot and reg across the 16-lane group
    #pragma unroll
    for (int off = 8; off >= 1; off >>= 1) {
        dot += __shfl_down_sync(0xFFFFFFFFu, dot, off);
        reg += __shfl_down_sync(0xFFFFFFFFu, reg, off);
    }

    __shared__ float sdata[16];
    if (lane == 0) {
        float contrib = 0.0f;
        if (row < BATCH) {
            float x = dot;
            // stable log_sigmoid(x) = min(x,0) - log1p(exp(-|x|))
            float ls = fminf(x, 0.0f) - log1pf(expf(-fabsf(x)));
            float d  = (float)s[row] - ls;
            contrib = d * d + reg;
        }
        sdata[grp] = contrib;
    }
    __syncthreads();

    if (tid < 16) {
        float v = sdata[tid];
        #pragma unroll
        for (int off = 8; off >= 1; off >>= 1)
            v += __shfl_down_sync(0xFFFFu, v, off);
        if (tid == 0)
            atomicAdd(out, v * (1.0f / (float)BATCH));
    }
}

extern "C" void kernel_launch(void* const* d_in, const int* in_sizes, int n_in,
                              void* d_out, int out_size) {
    const int*   u = (const int*)d_in[0];
    const int*   i = (const int*)d_in[1];
    const int*   s = (const int*)d_in[2];
    const float* W = (const float*)d_in[3];
    const float* H = (const float*)d_in[4];
    float* out = (float*)d_out;

    zero_out_kernel<<<1, 1>>>(out);
    pmf_kernel<<<BATCH / 16, 256>>>(u, i, s,
                                    (const float4*)W, (const float4*)H, out);
}